// round 2
// baseline (speedup 1.0000x reference)
#include <cuda_runtime.h>

#define HID 50
#define GCAP 131072
#define NMAX_ELEMS 50000000
#define ASTR 101
#define TILE 128

// ---------------- scratch (device globals; no allocations) ----------------
__device__ float  g_h[NMAX_ELEMS];
__device__ float  g_x[NMAX_ELEMS];
__device__ float  g_mean[(size_t)GCAP * HID];
__device__ float  g_invc[GCAP];
__device__ int    g_cnt[GCAP];
__device__ double g_sum[64];
__device__ double g_sq[64];
__device__ float  g_scale[64];
__device__ float  g_shift[64];

// ---------------- small utility kernels ----------------
__global__ void zero_cnt_k() {
    int i = blockIdx.x * blockDim.x + threadIdx.x;
    if (i < GCAP) g_cnt[i] = 0;
}

__global__ void count_k(const int* __restrict__ seg, int N) {
    int i = blockIdx.x * blockDim.x + threadIdx.x;
    if (i < N) atomicAdd(&g_cnt[seg[i]], 1);
}

__global__ void invc_k() {
    int i = blockIdx.x * blockDim.x + threadIdx.x;
    if (i < GCAP) {
        int c = g_cnt[i];
        g_invc[i] = 1.0f / (float)(c > 1 ? c : 1);
    }
}

__global__ void zero_mean_k() {
    int i = blockIdx.x * blockDim.x + threadIdx.x;
    if (i < GCAP * HID) g_mean[i] = 0.f;
    if (i < 64) { g_sum[i] = 0.0; g_sq[i] = 0.0; }
}

// node_init: h = xy @ w_init + b_init  (element-parallel, coalesced)
__global__ void init_k(const float* __restrict__ xy, const float* __restrict__ w,
                       const float* __restrict__ b, int NE) {
    int i = blockIdx.x * blockDim.x + threadIdx.x;
    if (i >= NE) return;
    int n = i / HID;
    int j = i - n * HID;
    g_h[i] = fmaf(xy[2 * n], w[j], fmaf(xy[2 * n + 1], w[HID + j], b[j]));
}

// segment sum of h into g_mean (sorted ids -> run-length accumulate, boundary atomics)
__global__ void segsum_k(const int* __restrict__ seg, int N) {
    __shared__ int ss[256];
    int base = blockIdx.x * 256;
    int cnt = N - base; if (cnt > 256) cnt = 256;
    for (int i = threadIdx.x; i < cnt; i += 64) ss[i] = seg[base + i];
    __syncthreads();
    int f = threadIdx.x;
    if (f >= HID) return;
    float acc = 0.f;
    int cur = ss[0];
    #pragma unroll 4
    for (int i = 0; i < cnt; i++) {
        float v = g_h[(size_t)(base + i) * HID + f];
        int s = ss[i];
        if (s != cur) {
            atomicAdd(&g_mean[(size_t)cur * HID + f], acc);
            acc = 0.f; cur = s;
        }
        acc += v;
    }
    atomicAdd(&g_mean[(size_t)cur * HID + f], acc);
}

// ---------------- fused MLP + BN-stats kernel ----------------
__global__ __launch_bounds__(128)
void mlp_k(const int* __restrict__ seg,
           const float* __restrict__ W1, const float* __restrict__ B1,
           const float* __restrict__ W2, const float* __restrict__ B2,
           int N) {
    extern __shared__ float sm[];
    float* s_w1  = sm;                 // 5000
    float* s_b1  = sm + 5000;          // 50
    float* s_w   = sm + 5050;          // 10000
    float* s_b2  = sm + 15050;         // 200
    float* s_sum = sm + 15250;         // 64
    float* s_sq  = sm + 15314;         // 64
    int*   s_seg = (int*)(sm + 15378); // 128
    float* act   = sm + 15506;         // 128 * 101

    int tid = threadIdx.x;
    for (int i = tid; i < 5000; i += 128)  s_w1[i] = W1[i];
    for (int i = tid; i < 10000; i += 128) s_w[i]  = W2[i];
    if (tid < HID) s_b1[tid] = B1[tid];
    for (int i = tid; i < 200; i += 128)   s_b2[i] = B2[i];
    if (tid < 64) { s_sum[tid] = 0.f; s_sq[tid] = 0.f; }

    int base = blockIdx.x * TILE;
    int cnt = N - base; if (cnt > TILE) cnt = TILE;
    if (tid < cnt) s_seg[tid] = seg[base + tid];
    __syncthreads();

    // stage tile: cols [0,50) = glob (gathered mean), cols [50,100) = h
    for (int idx = tid; idx < cnt * HID; idx += 128) {
        int n = idx / HID;
        int f = idx - n * HID;
        act[n * ASTR + HID + f] = g_h[(size_t)(base + n) * HID + f];
        int s = s_seg[n];
        act[n * ASTR + f] = g_mean[(size_t)s * HID + f] * g_invc[s];
    }
    __syncthreads();

    bool valid = tid < cnt;
    float acc[HID];
    if (valid) {
        float* row = act + tid * ASTR;
        // layer 1: 100 -> 50, relu
        #pragma unroll
        for (int j = 0; j < HID; j++) acc[j] = s_b1[j];
        #pragma unroll 1
        for (int k = 0; k < 2 * HID; k++) {
            float xk = row[k];
            const float* w = s_w1 + k * HID;
            #pragma unroll
            for (int j = 0; j < HID; j++) acc[j] = fmaf(xk, w[j], acc[j]);
        }
        #pragma unroll
        for (int j = 0; j < HID; j++) row[j] = fmaxf(acc[j], 0.f);
        // layers 2..5: 50 -> 50, relu on first 3
        #pragma unroll 1
        for (int l = 0; l < 4; l++) {
            const float* wl = s_w + l * (HID * HID);
            const float* bl = s_b2 + l * HID;
            #pragma unroll
            for (int j = 0; j < HID; j++) acc[j] = bl[j];
            #pragma unroll 1
            for (int k = 0; k < HID; k++) {
                float xk = row[k];
                const float* w = wl + k * HID;
                #pragma unroll
                for (int j = 0; j < HID; j++) acc[j] = fmaf(xk, w[j], acc[j]);
            }
            if (l < 3) {
                #pragma unroll
                for (int j = 0; j < HID; j++) row[j] = fmaxf(acc[j], 0.f);
            } else {
                #pragma unroll
                for (int j = 0; j < HID; j++) row[j] = acc[j];
            }
        }
    } else {
        #pragma unroll
        for (int j = 0; j < HID; j++) acc[j] = 0.f;
    }

    // BN partial stats: warp shuffle reduce -> smem atomics -> global double atomics
    #pragma unroll 1
    for (int j = 0; j < HID; j++) {
        float v = acc[j];
        float s1 = v, s2 = v * v;
        #pragma unroll
        for (int o = 16; o; o >>= 1) {
            s1 += __shfl_xor_sync(0xffffffffu, s1, o);
            s2 += __shfl_xor_sync(0xffffffffu, s2, o);
        }
        if ((tid & 31) == 0) {
            atomicAdd(&s_sum[j], s1);
            atomicAdd(&s_sq[j], s2);
        }
    }
    __syncthreads();
    if (tid < HID) {
        atomicAdd(&g_sum[tid], (double)s_sum[tid]);
        atomicAdd(&g_sq[tid], (double)s_sq[tid]);
    }

    // write pre-BN x tile, coalesced
    for (int idx = tid; idx < cnt * HID; idx += 128) {
        int n = idx / HID;
        int f = idx - n * HID;
        g_x[(size_t)(base + n) * HID + f] = act[n * ASTR + f];
    }
}

__global__ void finalize_k(const float* __restrict__ gamma,
                           const float* __restrict__ beta, double invN) {
    int f = threadIdx.x;
    if (f >= HID) return;
    double mu = g_sum[f] * invN;
    double var = g_sq[f] * invN - mu * mu;
    float istd = (float)rsqrt(var + 1e-5);
    float sc = istd * gamma[f];
    g_scale[f] = sc;
    g_shift[f] = fmaf(-(float)mu, sc, beta[f]);
}

__global__ void apply_k(float* __restrict__ dout, int to_h, int NE) {
    int i = blockIdx.x * blockDim.x + threadIdx.x;
    if (i >= NE) return;
    int f = i % HID;
    float v = fmaf(g_x[i], g_scale[f], g_shift[f]);
    if (to_h) g_h[i] = v;
    else      dout[i] = v;
}

// ---------------- launch ----------------
extern "C" void kernel_launch(void* const* d_in, const int* in_sizes, int n_in,
                              void* d_out, int out_size) {
    const float* xy     = (const float*)d_in[0];
    const int*   seg    = (const int*)  d_in[1];
    // d_in[2] = num_graphs (unused: GCAP capacity covers it)
    const float* w_init = (const float*)d_in[3];
    const float* b_init = (const float*)d_in[4];
    const float* Ws1    = (const float*)d_in[5];
    const float* bs1    = (const float*)d_in[6];
    const float* Ws     = (const float*)d_in[7];
    const float* bs     = (const float*)d_in[8];
    const float* gamma  = (const float*)d_in[9];
    const float* beta   = (const float*)d_in[10];
    float* out = (float*)d_out;

    int N  = in_sizes[1];       // number of nodes
    int NE = N * HID;

    const int smem_bytes = (15506 + TILE * ASTR) * (int)sizeof(float);
    cudaFuncSetAttribute(mlp_k, cudaFuncAttributeMaxDynamicSharedMemorySize, smem_bytes);

    // counts (once)
    zero_cnt_k<<<(GCAP + 255) / 256, 256>>>();
    count_k<<<(N + 255) / 256, 256>>>(seg, N);
    invc_k<<<(GCAP + 255) / 256, 256>>>();

    // node init
    init_k<<<(NE + 255) / 256, 256>>>(xy, w_init, b_init, NE);

    for (int i = 0; i < 2; i++) {
        zero_mean_k<<<(GCAP * HID + 255) / 256, 256>>>();
        segsum_k<<<(N + 255) / 256, 64>>>(seg, N);
        mlp_k<<<(N + TILE - 1) / TILE, 128, smem_bytes>>>(
            seg,
            Ws1 + i * (2 * HID * HID), bs1 + i * HID,
            Ws  + i * (4 * HID * HID), bs  + i * (4 * HID),
            N);
        finalize_k<<<1, 64>>>(gamma + i * HID, beta + i * HID, 1.0 / (double)N);
        apply_k<<<(NE + 255) / 256, 256>>>(out, i == 0 ? 1 : 0, NE);
    }
}